// round 12
// baseline (speedup 1.0000x reference)
#include <cuda_runtime.h>
#include <cuda_fp16.h>
#include <cstdint>
#include <math.h>

// staging: pooled-then-normalized fp32 protos; validity; compact LUT;
// fragment-major packed fp16 hi/lo proto images.
__device__ __align__(16) float g_protoF[256 * 256];
__device__ int g_valid[256];
__device__ int g_ci[256];
__device__ int g_map[256];
__device__ int g_vcnt;
// g_protoP[ct*4096 + ((tile*2+ks)*32 + lane)*8 + isL*4 + reg]
__device__ __align__(16) unsigned g_protoP[8 * 4096];

// ---- smem layout (4B units) ----
#define QS2  132          // Q tile row stride (16 kp rows x 132 px-u32)
#define OFF_A0  0         // 4096 u32 per A stage (fragment-major)
#define OFF_A1  4096
#define OFF_Q   8192      // 2 bufs x (QH 2112 + QL 2112)
#define QBUF    4224
#define SMEM_FLOATS 16640
#define SMEM_BYTES (SMEM_FLOATS * 4)   // 66.6 KB
// post-mainloop aliases (inside A region)
#define OFF_SQ  0         // 16 x 128
#define OFF_QN  2048      // 128
#define OFF_MM  2304      // 2 x 128
#define OFF_II  2560
#define OFF_SS  2816
#define OFF_WW  3072

__device__ __forceinline__ uint32_t s2u(const void* p) {
    uint32_t a;
    asm("{ .reg .u64 t; cvta.to.shared.u64 t, %1; cvt.u32.u64 %0, t; }"
        : "=r"(a) : "l"(p));
    return a;
}
__device__ __forceinline__ void cpasync16(uint32_t dst, const void* src) {
    size_t g = __cvta_generic_to_global(src);
    asm volatile("cp.async.cg.shared.global [%0], [%1], 16;"
                 :: "r"(dst), "l"(g) : "memory");
}
__device__ __forceinline__ uint32_t pack_h2(float a, float b) {
    __half_raw ra = (__half_raw)__float2half_rn(a);
    __half_raw rb = (__half_raw)__float2half_rn(b);
    return (uint32_t)ra.x | ((uint32_t)rb.x << 16);
}
__device__ __forceinline__ float h2f(float x) {
    return __half2float(__float2half_rn(x));
}
__device__ __forceinline__ void mma16(float* c, uint32_t a0, uint32_t a1,
                                      uint32_t a2, uint32_t a3,
                                      uint32_t b0, uint32_t b1) {
    asm volatile(
        "mma.sync.aligned.m16n8k16.row.col.f32.f16.f16.f32 "
        "{%0,%1,%2,%3}, {%4,%5,%6,%7}, {%8,%9}, {%0,%1,%2,%3};"
        : "+f"(c[0]), "+f"(c[1]), "+f"(c[2]), "+f"(c[3])
        : "r"(a0), "r"(a1), "r"(a2), "r"(a3), "r"(b0), "r"(b1));
}

// ---------------------------------------------------------------------------
// Kernel 1a: coalesced 8x8 avg-pool. block = (s,c) of 1024; 256 threads.
// writes unnormalized pooled value into g_protoF[p*256 + c].
// ---------------------------------------------------------------------------
__global__ void pool_kernel(const float* __restrict__ sup_x) {
    __shared__ float sh[4096];
    int sc = blockIdx.x;               // s*256 + c
    int s = sc >> 8, c = sc & 255;
    int t = threadIdx.x;
    const float4* src = (const float4*)(sup_x + (size_t)sc * 4096);
#pragma unroll
    for (int i = 0; i < 4; i++)
        *(float4*)(sh + (t + i * 256) * 4) = src[t + i * 256];
    __syncthreads();
    if (t < 64) {
        int i = t >> 3, j = t & 7;
        const float* base = sh + (i * 8) * 64 + j * 8;
        float sum = 0.f;
#pragma unroll
        for (int di = 0; di < 8; di++) {
            const float* r = base + di * 64;
            sum += ((r[0] + r[1]) + (r[2] + r[3])) + ((r[4] + r[5]) + (r[6] + r[7]));
        }
        int p = s * 64 + t;
        g_protoF[p * 256 + c] = sum * (1.0f / 64.0f);
    }
}

// ---------------------------------------------------------------------------
// Kernel 1b: per-proto normalize (in place) + validity
// ---------------------------------------------------------------------------
__global__ void norm_kernel(const float* __restrict__ sup_y) {
    __shared__ float sh[256];
    int p = blockIdx.x;
    int s = p >> 6, ij = p & 63, i = ij >> 3, j = ij & 7;
    int c = threadIdx.x;

    float f = g_protoF[p * 256 + c];
    sh[c] = f * f;
    __syncthreads();
    for (int st = 128; st > 0; st >>= 1) {
        if (c < st) sh[c] += sh[c + st];
        __syncthreads();
    }
    float inv = 1.0f / fmaxf(sqrtf(sh[0]), 1e-4f);
    g_protoF[p * 256 + c] = f * inv;
    __syncthreads();

    float m = 0.f;
    if (c < 64) {
        int di = c >> 3, dj = c & 7;
        float y = sup_y[(size_t)s * 4096 + (i * 8 + di) * 64 + (j * 8 + dj)];
        m = (y > 0.95f) ? 1.f : 0.f;
    }
    sh[c] = m;
    __syncthreads();
    for (int st = 128; st > 0; st >>= 1) {
        if (c < st) sh[c] += sh[c + st];
        __syncthreads();
    }
    if (c == 0) g_valid[p] = (sh[0] * (1.0f / 64.0f) > 0.5f) ? 1 : 0;
}

// ---------------------------------------------------------------------------
// Kernel 2a: scan (1 block)
// ---------------------------------------------------------------------------
__global__ void scan_kernel() {
    __shared__ int sc[256];
    int p = threadIdx.x;
    int v = g_valid[p];
    sc[p] = v;
    __syncthreads();
    for (int off = 1; off < 256; off <<= 1) {
        int add = (p >= off) ? sc[p - off] : 0;
        __syncthreads();
        sc[p] += add;
        __syncthreads();
    }
    int pos = sc[p];
    if (p == 255) g_vcnt = pos;
    g_ci[p] = pos - 1;
    if (v) g_map[pos - 1] = p;
}

// ---------------------------------------------------------------------------
// Kernel 2b: fragment-major pack (256 blocks x 128 thr) + proto_grid out
// ---------------------------------------------------------------------------
__global__ void pack_kernel(const float* __restrict__ sup_y,
                            float* __restrict__ out) {
    int p = blockIdx.x, t = threadIdx.x;
    if (t < 64) {
        int idx = p * 64 + t;
        out[262144 + idx] = (sup_y[idx] > 0.95f) ? 1.f : 0.f;
    }
    if (g_valid[p]) {
        int ci = g_ci[p];
        int t_tile = ci >> 4, m_local = ci & 15;
        int ct = t >> 4, kp = t & 15;
        int ks = kp >> 3, ka = kp & 3, mid = (kp >> 2) & 1;
        int lane = (m_local & 7) * 4 + ka;
        int reg = mid * 2 + (m_local >> 3);
        const float* src = g_protoF + p * 256;
        float v0 = src[ct * 32 + 2 * kp];
        float v1 = src[ct * 32 + 2 * kp + 1];
        uint32_t base = ct * 4096 + ((t_tile * 2 + ks) * 32 + lane) * 8 + reg;
        g_protoP[base]     = pack_h2(v0, v1);
        g_protoP[base + 4] = pack_h2(v0 - h2f(v0), v1 - h2f(v1));
    }
}

// ---------------------------------------------------------------------------
// Kernel 3: 3x fp16-split mma.sync(k16), fragment-major A, shuffle epilogue
// grid = 32 batches * 32 tiles(128 px) ; 256 threads, 8 warps (2 wm x 4 wn)
// ---------------------------------------------------------------------------
__global__ void __launch_bounds__(256, 2)
dist_kernel(const float* __restrict__ qry, float* __restrict__ out) {
    extern __shared__ __align__(16) float sm[];
    float* SQ = sm + OFF_SQ;
    float* QN = sm + OFF_QN;
    float* MMs = sm + OFF_MM;
    int*   IIs = (int*)(sm + OFF_II);
    float* SSs = sm + OFF_SS;
    float* WWs = sm + OFF_WW;

    int tid = threadIdx.x, w = tid >> 5, l = tid & 31;
    int wm = w & 1, wn = w >> 1;

    const int V = g_vcnt;
    const int nTiles = (V + 15) >> 4;
    const int nTu32 = nTiles * 512;          // u32 per A chunk actually used
    int tmax = (nTiles + 1 - wm) >> 1;
    if (tmax > 4) tmax = 4;

    int b = blockIdx.x >> 5, n0 = (blockIdx.x & 31) << 7;
    const float* Qbase = qry + (size_t)b * 256 * 4096 + n0;

    float acc[4][4][4];
#pragma unroll
    for (int tm = 0; tm < 4; tm++)
#pragma unroll
        for (int tn = 0; tn < 4; tn++)
#pragma unroll
            for (int e = 0; e < 4; e++) acc[tm][tn][e] = 0.f;

    float4 qe0, qe1, qo0, qo1;
    float ssq8[8];
#pragma unroll
    for (int e = 0; e < 8; e++) ssq8[e] = 0.f;
    const int kp0 = tid >> 4, nf = tid & 15;
    const int ka = l & 3, ga = l >> 2;

#define Q_LOAD(ctv)                                                            \
    {                                                                          \
        const float* qc = Qbase + (size_t)((ctv) * 32 + 2 * kp0) * 4096 + nf * 8; \
        qe0 = *(const float4*)(qc);                                            \
        qe1 = *(const float4*)(qc + 4);                                        \
        qo0 = *(const float4*)(qc + 4096);                                     \
        qo1 = *(const float4*)(qc + 4100);                                     \
    }

#define SPLIT_STORE(QHdst, QLdst)                                              \
    {                                                                          \
        float ev[8] = {qe0.x, qe0.y, qe0.z, qe0.w, qe1.x, qe1.y, qe1.z, qe1.w};\
        float od[8] = {qo0.x, qo0.y, qo0.z, qo0.w, qo1.x, qo1.y, qo1.z, qo1.w};\
        uint32_t hq[8], lq[8];                                                 \
        _Pragma("unroll")                                                      \
        for (int e = 0; e < 8; e++) {                                          \
            hq[e] = pack_h2(ev[e], od[e]);                                     \
            lq[e] = pack_h2(ev[e] - h2f(ev[e]), od[e] - h2f(od[e]));           \
            ssq8[e] = fmaf(ev[e], ev[e], fmaf(od[e], od[e], ssq8[e]));         \
        }                                                                      \
        float* hb = (QHdst) + kp0 * QS2 + nf * 8;                              \
        float* lb = (QLdst) + kp0 * QS2 + nf * 8;                              \
        *(uint4*)hb       = make_uint4(hq[0], hq[1], hq[2], hq[3]);            \
        *(uint4*)(hb + 4) = make_uint4(hq[4], hq[5], hq[6], hq[7]);            \
        *(uint4*)lb       = make_uint4(lq[0], lq[1], lq[2], lq[3]);            \
        *(uint4*)(lb + 4) = make_uint4(lq[4], lq[5], lq[6], lq[7]);            \
    }

#define A_LOAD(dstf, ctv)                                                      \
    _Pragma("unroll")                                                          \
    for (int i = 0; i < 4; i++) {                                              \
        int o4 = (tid + i * 256) * 4;                                          \
        if (o4 < nTu32)                                                        \
            cpasync16(s2u((dstf) + o4), g_protoP + (ctv) * 4096 + o4);         \
    }

    // ---- prologue ----
    {
        A_LOAD(sm + OFF_A0, 0)
        asm volatile("cp.async.commit_group;" ::: "memory");
        Q_LOAD(0)
        float* QHd = sm + OFF_Q;
        SPLIT_STORE(QHd, QHd + 2112)
        Q_LOAD(1)
    }

    for (int ct = 0; ct < 8; ct++) {
        int stg = ct & 1;
        float* A  = sm + (stg ? OFF_A1 : OFF_A0);
        float* QH = sm + OFF_Q + stg * QBUF;
        float* QL = QH + 2112;

        asm volatile("cp.async.wait_group 0;" ::: "memory");
        __syncthreads();

        if (ct < 7) {
            float* An = sm + (stg ? OFF_A0 : OFF_A1);
            A_LOAD(An, ct + 1)
            asm volatile("cp.async.commit_group;" ::: "memory");

            float* QHd = sm + OFF_Q + (stg ^ 1) * QBUF;
            SPLIT_STORE(QHd, QHd + 2112)
            if (ct < 6) Q_LOAD(ct + 2)
        }

#pragma unroll
        for (int ks = 0; ks < 2; ks++) {
            uint32_t bh[4][2], bl[4][2];
            const int qb = (ks * 8 + ka) * QS2 + wn * 32 + ga;
#pragma unroll
            for (int tn = 0; tn < 4; tn++) {
                bh[tn][0] = __float_as_uint(QH[qb + tn * 8]);
                bh[tn][1] = __float_as_uint(QH[qb + tn * 8 + 4 * QS2]);
                bl[tn][0] = __float_as_uint(QL[qb + tn * 8]);
                bl[tn][1] = __float_as_uint(QL[qb + tn * 8 + 4 * QS2]);
            }
#pragma unroll
            for (int tm = 0; tm < 4; tm++) {
                if (tm < tmax) {
                    int t = tm * 2 + wm;
                    const float* fa = A + ((t * 2 + ks) * 32 + l) * 8;
                    uint4 H = *(const uint4*)fa;
                    uint4 L = *(const uint4*)(fa + 4);
#pragma unroll
                    for (int tn = 0; tn < 4; tn++) {
                        mma16(acc[tm][tn], H.x, H.y, H.z, H.w, bh[tn][0], bh[tn][1]);
                        mma16(acc[tm][tn], H.x, H.y, H.z, H.w, bl[tn][0], bl[tn][1]);
                        mma16(acc[tm][tn], L.x, L.y, L.z, L.w, bh[tn][0], bh[tn][1]);
                    }
                }
            }
        }
    }

    __syncthreads();

    // ---- qnorm reduction (deterministic) ----
    {
        float* sq = SQ + kp0 * 128 + nf * 8;
        *(float4*)sq       = make_float4(ssq8[0], ssq8[1], ssq8[2], ssq8[3]);
        *(float4*)(sq + 4) = make_float4(ssq8[4], ssq8[5], ssq8[6], ssq8[7]);
    }
    __syncthreads();
    if (tid < 128) {
        float s = 0.f;
#pragma unroll
        for (int j = 0; j < 16; j++) s += SQ[j * 128 + tid];
        QN[tid] = 20.0f / fmaxf(sqrtf(s), 1e-4f);
    }
    __syncthreads();

    // ---- shuffle epilogue: per-(tn,par) pixel reduction over this warp ----
    const float NEG = __int_as_float(0xff800000);
#pragma unroll
    for (int tn = 0; tn < 4; tn++) {
#pragma unroll
        for (int par = 0; par < 2; par++) {
            int nloc = wn * 32 + tn * 8 + 2 * ka + par;
            float scl = QN[nloc];

            // pass 1: local max/argmax over this lane's 8 protos (ascending c)
            float m = NEG; int idx = 0;
#pragma unroll
            for (int tm = 0; tm < 4; tm++) {
                if (tm < tmax) {
                    int t = tm * 2 + wm;
#pragma unroll
                    for (int hi = 0; hi < 2; hi++) {
                        int c = t * 16 + ga + 8 * hi;
                        if (c < V) {
                            float d = acc[tm][tn][par + 2 * hi] * scl;
                            if (d > m) { m = d; idx = c; }
                        }
                    }
                }
            }
            // bfly reduce over the 8 ga-lanes (masks 4,8,16)
#pragma unroll
            for (int msk = 4; msk <= 16; msk <<= 1) {
                float om = __shfl_xor_sync(0xffffffffu, m, msk);
                int oi = __shfl_xor_sync(0xffffffffu, idx, msk);
                if (om > m || (om == m && oi < idx)) { m = om; idx = oi; }
            }
            // pass 2: exp sums against group max
            float se = 0.f, ws = 0.f;
#pragma unroll
            for (int tm = 0; tm < 4; tm++) {
                if (tm < tmax) {
                    int t = tm * 2 + wm;
#pragma unroll
                    for (int hi = 0; hi < 2; hi++) {
                        int c = t * 16 + ga + 8 * hi;
                        if (c < V) {
                            float d = acc[tm][tn][par + 2 * hi] * scl;
                            float e = __expf(d - m);
                            se += e; ws = fmaf(e, d, ws);
                        }
                    }
                }
            }
#pragma unroll
            for (int msk = 4; msk <= 16; msk <<= 1) {
                se += __shfl_xor_sync(0xffffffffu, se, msk);
                ws += __shfl_xor_sync(0xffffffffu, ws, msk);
            }
            if (ga == 0) {
                MMs[wm * 128 + nloc] = m;
                IIs[wm * 128 + nloc] = idx;
                SSs[wm * 128 + nloc] = se;
                WWs[wm * 128 + nloc] = ws;
            }
        }
    }
    __syncthreads();

    // ---- merge the two wm halves per pixel ----
    if (tid < 128) {
        float m0 = MMs[tid], m1 = MMs[128 + tid];
        int i0 = IIs[tid], i1 = IIs[128 + tid];
        float M; int I;
        if (m1 > m0 || (m1 == m0 && i1 < i0)) { M = m1; I = i1; }
        else                                   { M = m0; I = i0; }
        float e0 = __expf(m0 - M), e1 = __expf(m1 - M);
        float SE = SSs[tid] * e0 + SSs[128 + tid] * e1;
        float WS = WWs[tid] * e0 + WWs[128 + tid] * e1;
        size_t o = (size_t)b * 4096 + n0 + tid;
        out[o] = WS / SE;
        out[131072 + o] = (float)__ldg(&g_map[I]);
    }
}

extern "C" void kernel_launch(void* const* d_in, const int* in_sizes, int n_in,
                              void* d_out, int out_size) {
    const float* qry   = (const float*)d_in[0];
    const float* sup_x = (const float*)d_in[1];
    const float* sup_y = (const float*)d_in[2];
    float* out = (float*)d_out;

    cudaFuncSetAttribute(dist_kernel,
                         cudaFuncAttributeMaxDynamicSharedMemorySize, SMEM_BYTES);

    pool_kernel<<<1024, 256>>>(sup_x);
    norm_kernel<<<256, 256>>>(sup_y);
    scan_kernel<<<1, 256>>>();
    pack_kernel<<<256, 128>>>(sup_y, out);
    dist_kernel<<<1024, 256, SMEM_BYTES>>>(qry, out);
}